// round 3
// baseline (speedup 1.0000x reference)
#include <cuda_runtime.h>
#include <cstdint>

#define CC 128
#define LL 1024
#define OO 128
#define PP 1017
#define FF 8
#define OB 64           // o rows per block
#define NB 32           // batches
#define CPC 4           // channels per chunk
#define KC (CPC*FF)     // 32 k per chunk
#define NCHUNK (CC/CPC) // 32 chunks
#define W 36            // smem row pitch (floats): 144B, 16B-aligned, odd multiple of 16B
#define STG 2

#define OSTR ((long long)CC * PP * FF)  // filt o-stride (floats)
#define CSTR ((long long)PP * FF)       // filt c-stride (floats)

__device__ __forceinline__ unsigned long long pack2(float lo, float hi) {
    unsigned long long r;
    asm("mov.b64 %0, {%1, %2};" : "=l"(r) : "f"(lo), "f"(hi));
    return r;
}
__device__ __forceinline__ void fma2(unsigned long long& d, unsigned long long a, unsigned long long b) {
    asm("fma.rn.f32x2 %0, %1, %2, %0;" : "+l"(d) : "l"(a), "l"(b));
}
__device__ __forceinline__ void unpack2(unsigned long long v, float& lo, float& hi) {
    asm("mov.b64 {%0, %1}, %2;" : "=f"(lo), "=f"(hi) : "l"(v));
}
__device__ __forceinline__ void cp16(uint32_t dst, const void* src) {
    asm volatile("cp.async.cg.shared.global [%0], [%1], 16;\n" :: "r"(dst), "l"(src));
}
__device__ __forceinline__ void cp4(uint32_t dst, const void* src) {
    asm volatile("cp.async.ca.shared.global [%0], [%1], 4;\n" :: "r"(dst), "l"(src));
}
#define CP_COMMIT() asm volatile("cp.async.commit_group;\n" ::: "memory")
#define CP_WAIT0()  asm volatile("cp.async.wait_group 0;\n" ::: "memory")

__global__ __launch_bounds__(64, 7) void loc1d_kernel(
    const float* __restrict__ x, const float* __restrict__ filt, float* __restrict__ out)
{
    __shared__ __align__(16) float As[STG][OB][W];  // [stage][o][k] — gmem order, k contiguous
    __shared__ __align__(16) float Bs[STG][NB][W];  // [stage][b][k]

    const int p     = blockIdx.x;
    const int obase = blockIdx.y * OB;
    const int tid   = threadIdx.x;
    const int otid  = tid >> 2;  // 0..15
    const int btid  = tid & 3;   // 0..3

    const uint32_t as_u = (uint32_t)__cvta_generic_to_shared(&As[0][0][0]);
    const uint32_t bs_u = (uint32_t)__cvta_generic_to_shared(&Bs[0][0][0]);

    const float* fbase = filt + (long long)obase * OSTR + (long long)p * FF;

    unsigned long long acc[4][4];  // [o-idx][b-pair] = 32 fp32
#pragma unroll
    for (int i = 0; i < 4; i++)
#pragma unroll
        for (int j = 0; j < 4; j++) acc[i][j] = 0ull;

    // ---- async chunk loader: filt 64o x 4c x 8f (16B ops), x 32b x 4c x 8f (4B ops) ----
    auto load_chunk = [&](int ch, int s) {
        const int c0 = ch * CPC;
#pragma unroll
        for (int i = 0; i < 8; i++) {          // 512 x 16B total
            int v  = tid + 64 * i;
            int fh = v & 1;
            int o6 = (v >> 1) & 63;
            int cp = v >> 7;
            const float* src = fbase + (long long)o6 * OSTR + (long long)(c0 + cp) * CSTR + fh * 4;
            uint32_t dst = as_u + (uint32_t)(((s * OB + o6) * W + cp * 8 + fh * 4) * 4);
            cp16(dst, src);
        }
#pragma unroll
        for (int i = 0; i < 16; i++) {         // 1024 x 4B total (p-unaligned)
            int v  = tid + 64 * i;
            int f  = v & 7;
            int b  = (v >> 3) & 31;
            int cp = (v >> 8) & 3;
            const float* src = x + ((long long)b * CC + (c0 + cp)) * LL + p + f;
            uint32_t dst = bs_u + (uint32_t)(((s * NB + b) * W + cp * 8 + f) * 4);
            cp4(dst, src);
        }
    };

    load_chunk(0, 0);
    CP_COMMIT();

    for (int ch = 0; ch < NCHUNK; ch++) {
        const int s = ch & 1;
        CP_WAIT0();
        __syncthreads();                 // data visible + prev compute done on buffer s^1
        if (ch + 1 < NCHUNK) load_chunk(ch + 1, s ^ 1);
        CP_COMMIT();                     // always commit (possibly empty) to keep count

        // ---- compute: 32 k as 8 quads, strided register tile 4o x 8b ----
#pragma unroll
        for (int q = 0; q < KC / 4; q++) {
            float av[4][4], bv[8][4];
#pragma unroll
            for (int i = 0; i < 4; i++)
                *reinterpret_cast<float4*>(av[i]) =
                    *reinterpret_cast<const float4*>(&As[s][otid + 16 * i][q * 4]);
#pragma unroll
            for (int j = 0; j < 8; j++)
                *reinterpret_cast<float4*>(bv[j]) =
                    *reinterpret_cast<const float4*>(&Bs[s][btid + 4 * j][q * 4]);
#pragma unroll
            for (int kk = 0; kk < 4; kk++) {
                unsigned long long bp[4];
#pragma unroll
                for (int jp = 0; jp < 4; jp++)
                    bp[jp] = pack2(bv[2 * jp][kk], bv[2 * jp + 1][kk]);
#pragma unroll
                for (int i = 0; i < 4; i++) {
                    unsigned long long ap = pack2(av[i][kk], av[i][kk]);
#pragma unroll
                    for (int jp = 0; jp < 4; jp++) fma2(acc[i][jp], ap, bp[jp]);
                }
            }
        }
    }

    // ---- epilogue: scale by (C*F)^-0.5 = 1/32, scatter ----
    const float scale = 0.03125f;
#pragma unroll
    for (int i = 0; i < 4; i++) {
        const int o = obase + otid + 16 * i;
        float* op = out + (long long)o * PP + p;
#pragma unroll
        for (int jp = 0; jp < 4; jp++) {
            float lo, hi;
            unpack2(acc[i][jp], lo, hi);
            const int b = btid + 8 * jp;
            op[(long long)b * (OO * PP)]       = lo * scale;
            op[(long long)(b + 4) * (OO * PP)] = hi * scale;
        }
    }
}

extern "C" void kernel_launch(void* const* d_in, const int* in_sizes, int n_in,
                              void* d_out, int out_size) {
    const float* x    = (const float*)d_in[0];
    const float* filt = (const float*)d_in[1];
    float* out        = (float*)d_out;
    dim3 grid(PP, OO / OB);
    loc1d_kernel<<<grid, 64>>>(x, filt, out);
}